// round 2
// baseline (speedup 1.0000x reference)
#include <cuda_runtime.h>
#include <math.h>

#define B_   2
#define T_   2048
#define D_   2048
#define HQ_  16
#define HK_  4
#define HD_  128
#define MROWS (B_*T_)            // 4096
#define QELEMS (MROWS*HQ_*HD_)   // 8388608
#define KVELEMS (MROWS*HK_*HD_)  // 2097152

// scratch (no allocations allowed)
__device__ float g_q[QELEMS];
__device__ float g_kraw[KVELEMS];
__device__ float g_vraw[KVELEMS];
__device__ float g_attn[QELEMS];

// ---------------------------------------------------------------- SGEMM 64x64
// C[M,N] = A[M,K] @ B[K,N], all row-major, M,N multiples of 64, K multiple of 16
__global__ void sgemm64(const float* __restrict__ A, const float* __restrict__ Bm,
                        float* __restrict__ C, int N, int K) {
    __shared__ float As[16][68];   // A^T tile: As[k][m]
    __shared__ float Bs[16][68];   // Bs[k][n]
    int tid = threadIdx.x;                 // 256 threads
    int ty = tid >> 4, tx = tid & 15;
    long row0 = (long)blockIdx.y * 64;
    int col0 = blockIdx.x * 64;
    float acc[4][4];
    #pragma unroll
    for (int r = 0; r < 4; r++)
        #pragma unroll
        for (int c = 0; c < 4; c++) acc[r][c] = 0.f;

    int ar = tid >> 2, ak = (tid & 3) << 2;
    int bk = tid >> 4, bc = (tid & 15) << 2;

    for (int kt = 0; kt < K; kt += 16) {
        float4 av = *(const float4*)(A + (row0 + ar) * K + kt + ak);
        As[ak + 0][ar] = av.x; As[ak + 1][ar] = av.y;
        As[ak + 2][ar] = av.z; As[ak + 3][ar] = av.w;
        *(float4*)&Bs[bk][bc] = *(const float4*)(Bm + (long)(kt + bk) * N + col0 + bc);
        __syncthreads();
        #pragma unroll
        for (int kk = 0; kk < 16; kk++) {
            float4 a  = *(const float4*)&As[kk][ty << 2];
            float4 bv = *(const float4*)&Bs[kk][tx << 2];
            float aa[4] = {a.x, a.y, a.z, a.w};
            float bb[4] = {bv.x, bv.y, bv.z, bv.w};
            #pragma unroll
            for (int r = 0; r < 4; r++)
                #pragma unroll
                for (int c = 0; c < 4; c++) acc[r][c] += aa[r] * bb[c];
        }
        __syncthreads();
    }
    #pragma unroll
    for (int r = 0; r < 4; r++) {
        float4 o = make_float4(acc[r][0], acc[r][1], acc[r][2], acc[r][3]);
        *(float4*)(C + (row0 + (ty << 2) + r) * N + col0 + (tx << 2)) = o;
    }
}

// ---------------------------------------------------------------- RoPE + pack
// q: in-place rope + fold 1/sqrt(128); k: rope -> kv cache; v: copy -> kv cache
__global__ void rope_pack(float* __restrict__ q, const float* __restrict__ kraw,
                          const float* __restrict__ vraw, float* __restrict__ kv) {
    int idx = blockIdx.x * 256 + threadIdx.x;   // 4194304 threads (q pairs)
    {
        int row = idx >> 10;          // (b*T + t)
        int rem = idx & 1023;
        int h = rem >> 6, m = rem & 63;
        int t = row & (T_ - 1);
        float invf = powf(10000.0f, -(float)(2 * m) * (1.0f / 128.0f));
        float ang = (float)t * invf;
        float c = cosf(ang), s = sinf(ang);
        const float scale = 0.08838834764831845f;   // 1/sqrt(128)
        long base = (long)row * (HQ_ * HD_) + h * HD_ + m;
        float x1 = q[base], x2 = q[base + 64];
        q[base]      = (x1 * c - x2 * s) * scale;
        q[base + 64] = (x2 * c + x1 * s) * scale;
    }
    if (idx < MROWS * HK_ * 64) {   // k pairs: 1048576
        int krow = idx >> 8;
        int krem = idx & 255;
        int kh = krem >> 6, km = krem & 63;
        int kt = krow & (T_ - 1);
        float invf = powf(10000.0f, -(float)(2 * km) * (1.0f / 128.0f));
        float ang = (float)kt * invf;
        float c = cosf(ang), s = sinf(ang);
        long src = (long)krow * (HK_ * HD_) + kh * HD_ + km;
        float x1 = kraw[src], x2 = kraw[src + 64];
        long dst = ((long)krow * HK_ + kh) * 256 + km;
        kv[dst]      = x1 * c - x2 * s;
        kv[dst + 64] = x2 * c + x1 * s;
    }
    if (idx < KVELEMS / 4) {        // v float4 copies: 524288
        int f = idx;
        int vrow = f >> 7;            // 128 float4 per row of 512
        int vc4 = f & 127;
        int vh = vc4 >> 5, vd4 = (vc4 & 31) << 2;
        float4 v = *(const float4*)(vraw + (long)f * 4);
        long dst = ((long)vrow * HK_ + vh) * 256 + 128 + vd4;
        *(float4*)(kv + dst) = v;
    }
}

// ---------------------------------------------------------------- threefry2x32
__device__ __forceinline__ unsigned tf_rotl(unsigned x, int r) {
    return (x << r) | (x >> (32 - r));
}
// JAX threefry PARTITIONABLE path (default since jax 0.4.30):
// per-element 64-bit counter e: x0 = hi32(e) (= 0 here), x1 = lo32(e);
// 32-bit output = out0 ^ out1. Key from jax.random.key(1) = (0, 1).
__device__ __forceinline__ float dropout_keep(unsigned e) {
    unsigned x0 = 0u, x1 = e;
    const unsigned k0 = 0u, k1 = 1u, k2 = 0x1BD11BDAu ^ k0 ^ k1;
    x0 += k0; x1 += k1;
#define TFR(r) { x0 += x1; x1 = tf_rotl(x1, r); x1 ^= x0; }
    TFR(13) TFR(15) TFR(26) TFR(6)
    x0 += k1; x1 += k2 + 1u;
    TFR(17) TFR(29) TFR(16) TFR(24)
    x0 += k2; x1 += k0 + 2u;
    TFR(13) TFR(15) TFR(26) TFR(6)
    x0 += k0; x1 += k1 + 3u;
    TFR(17) TFR(29) TFR(16) TFR(24)
    x0 += k1; x1 += k2 + 4u;
    TFR(13) TFR(15) TFR(26) TFR(6)
    x0 += k2; x1 += k0 + 5u;
#undef TFR
    unsigned bits = x0 ^ x1;
    float u = __uint_as_float((bits >> 9) | 0x3F800000u) - 1.0f;
    return (u < 0.9f) ? (1.0f / 0.9f) : 0.0f;
}

// ---------------------------------------------------------------- attention
// grid: (T/64, B*HQ), 256 threads. Flash-style with online softmax + dropout.
#define ATT_SMEM_FLOATS (128*68 + 128*68 + 64*128 + 64*64)
__global__ void attn_kernel(const float* __restrict__ Q, const float* __restrict__ KV,
                            float* __restrict__ O) {
    extern __shared__ float sm[];
    float* Qts = sm;                 // [128][68] transposed
    float* Kts = sm + 128 * 68;      // [128][68] transposed
    float* Vs  = Kts + 128 * 68;     // [64][128] row-major
    float* Pts = Vs + 64 * 128;      // [64][64]  swizzled, P^T[j][i]

    int tid = threadIdx.x;
    int ty = tid >> 4, tx = tid & 15;
    int qb = (gridDim.x - 1) - blockIdx.x;   // heavy blocks first
    int bh = blockIdx.y;
    int b = bh >> 4, hq = bh & 15;
    int hk = hq & 3;                          // GQA: kv head = hq % 4

    // load Q tile transposed (stores conflict-free; global semi-coalesced, tiny volume)
    #pragma unroll
    for (int l = 0; l < 8; l++) {
        int lin = tid + (l << 8);
        int r = lin & 63;
        int d4 = (lin >> 6) << 2;
        const float* src = Q + (long)(b * T_ + qb * 64 + r) * (HQ_ * HD_) + hq * HD_ + d4;
        float4 v = *(const float4*)src;
        float* dst = Qts + d4 * 68 + r;
        dst[0] = v.x; dst[68] = v.y; dst[136] = v.z; dst[204] = v.w;
    }

    float m_i[4], l_i[4], o[4][8];
    #pragma unroll
    for (int r = 0; r < 4; r++) {
        m_i[r] = -INFINITY; l_i[r] = 0.f;
        #pragma unroll
        for (int c = 0; c < 8; c++) o[r][c] = 0.f;
    }
    unsigned ebase = (unsigned)(b * 16 + hq) * 4194304u;  // * 2048*2048

    for (int jb = 0; jb <= qb; jb++) {
        // K transposed + V row-major
        #pragma unroll
        for (int l = 0; l < 8; l++) {
            int lin = tid + (l << 8);
            int r = lin & 63;
            int d4 = (lin >> 6) << 2;
            const float* ksrc = KV + ((long)(b * T_ + jb * 64 + r) * HK_ + hk) * 256 + d4;
            float4 v = *(const float4*)ksrc;
            float* dst = Kts + d4 * 68 + r;
            dst[0] = v.x; dst[68] = v.y; dst[136] = v.z; dst[204] = v.w;
            int r2 = lin >> 5;
            int e4 = (lin & 31) << 2;
            const float* vsrc = KV + ((long)(b * T_ + jb * 64 + r2) * HK_ + hk) * 256 + 128 + e4;
            *(float4*)(Vs + r2 * 128 + e4) = *(const float4*)vsrc;
        }
        __syncthreads();

        // S = Q K^T (q pre-scaled by 1/sqrt(128))
        float s[4][4];
        #pragma unroll
        for (int r = 0; r < 4; r++)
            #pragma unroll
            for (int c = 0; c < 4; c++) s[r][c] = 0.f;
        #pragma unroll 8
        for (int d = 0; d < 128; d++) {
            float4 a  = *(const float4*)(Qts + d * 68 + (ty << 2));
            float4 bq = *(const float4*)(Kts + d * 68 + (tx << 2));
            float aa[4] = {a.x, a.y, a.z, a.w};
            float bb[4] = {bq.x, bq.y, bq.z, bq.w};
            #pragma unroll
            for (int r = 0; r < 4; r++)
                #pragma unroll
                for (int c = 0; c < 4; c++) s[r][c] += aa[r] * bb[c];
        }
        if (jb == qb) {   // causal diagonal block
            #pragma unroll
            for (int r = 0; r < 4; r++)
                #pragma unroll
                for (int c = 0; c < 4; c++)
                    if ((tx << 2) + c > (ty << 2) + r) s[r][c] = -1e30f;
        }

        // online softmax + dropout, write P^T to smem (swizzled)
        #pragma unroll
        for (int r = 0; r < 4; r++) {
            float rm = fmaxf(fmaxf(s[r][0], s[r][1]), fmaxf(s[r][2], s[r][3]));
            #pragma unroll
            for (int off = 8; off; off >>= 1)
                rm = fmaxf(rm, __shfl_xor_sync(0xffffffffu, rm, off, 16));
            float mnew = fmaxf(m_i[r], rm);
            float corr = expf(m_i[r] - mnew);
            float p[4], rs = 0.f;
            #pragma unroll
            for (int c = 0; c < 4; c++) { p[c] = expf(s[r][c] - mnew); rs += p[c]; }
            #pragma unroll
            for (int off = 8; off; off >>= 1)
                rs += __shfl_xor_sync(0xffffffffu, rs, off, 16);
            l_i[r] = l_i[r] * corr + rs;   // denominator WITHOUT dropout (matches ref)
            m_i[r] = mnew;
            #pragma unroll
            for (int c = 0; c < 8; c++) o[r][c] *= corr;

            unsigned ig = (unsigned)(qb * 64 + (ty << 2) + r);
            unsigned jg0 = (unsigned)(jb * 64 + (tx << 2));
            int i = (ty << 2) + r;
            #pragma unroll
            for (int c = 0; c < 4; c++) {
                float pd = p[c] * dropout_keep(ebase + ig * 2048u + jg0 + (unsigned)c);
                int j = (tx << 2) + c;
                Pts[j * 64 + (((i >> 2) ^ (j & 15)) << 2) + (i & 3)] = pd;
            }
        }
        __syncthreads();

        // O += P V
        #pragma unroll 4
        for (int j = 0; j < 64; j++) {
            float4 a  = *(const float4*)(Pts + j * 64 + ((ty ^ (j & 15)) << 2));
            float4 b1 = *(const float4*)(Vs + j * 128 + (tx << 2));
            float4 b2 = *(const float4*)(Vs + j * 128 + 64 + (tx << 2));
            float aa[4] = {a.x, a.y, a.z, a.w};
            float bb[8] = {b1.x, b1.y, b1.z, b1.w, b2.x, b2.y, b2.z, b2.w};
            #pragma unroll
            for (int r = 0; r < 4; r++)
                #pragma unroll
                for (int c = 0; c < 8; c++) o[r][c] += aa[r] * bb[c];
        }
        __syncthreads();
    }

    // epilogue: normalize and store
    #pragma unroll
    for (int r = 0; r < 4; r++) {
        float inv = 1.0f / l_i[r];
        long base = (long)(b * T_ + qb * 64 + (ty << 2) + r) * (HQ_ * HD_) + hq * HD_;
        float4 o1 = make_float4(o[r][0] * inv, o[r][1] * inv, o[r][2] * inv, o[r][3] * inv);
        float4 o2 = make_float4(o[r][4] * inv, o[r][5] * inv, o[r][6] * inv, o[r][7] * inv);
        *(float4*)(O + base + (tx << 2)) = o1;
        *(float4*)(O + base + 64 + (tx << 2)) = o2;
    }
}

// ---------------------------------------------------------------- launch
extern "C" void kernel_launch(void* const* d_in, const int* in_sizes, int n_in,
                              void* d_out, int out_size) {
    const float* x  = (const float*)d_in[0];
    const float* wq = (const float*)d_in[1];
    const float* wk = (const float*)d_in[2];
    const float* wv = (const float*)d_in[3];
    const float* wo = (const float*)d_in[4];
    float* out = (float*)d_out;              // attn_output [2,2048,2048]
    float* kv  = out + QELEMS;               // new_kv_cache [2,2048,4,256]

    float *qp, *kp, *vp, *ap;
    cudaGetSymbolAddress((void**)&qp, g_q);
    cudaGetSymbolAddress((void**)&kp, g_kraw);
    cudaGetSymbolAddress((void**)&vp, g_vraw);
    cudaGetSymbolAddress((void**)&ap, g_attn);

    dim3 blk(256);
    sgemm64<<<dim3(D_ / 64, MROWS / 64), blk>>>(x, wq, qp, D_, D_);          // q
    sgemm64<<<dim3((HK_ * HD_) / 64, MROWS / 64), blk>>>(x, wk, kp, HK_ * HD_, D_); // k
    sgemm64<<<dim3((HK_ * HD_) / 64, MROWS / 64), blk>>>(x, wv, vp, HK_ * HD_, D_); // v

    rope_pack<<<(MROWS * HQ_ * 64) / 256, 256>>>(qp, kp, vp, kv);

    int smem = ATT_SMEM_FLOATS * 4;
    cudaFuncSetAttribute(attn_kernel, cudaFuncAttributeMaxDynamicSharedMemorySize, smem);
    attn_kernel<<<dim3(T_ / 64, B_ * HQ_), 256, smem>>>(qp, kv, ap);

    sgemm64<<<dim3(D_ / 64, MROWS / 64), blk>>>(ap, wo, out, D_, D_);        // out proj
}

// round 4
// speedup vs baseline: 1.7493x; 1.7493x over previous
#include <cuda_runtime.h>
#include <cuda_bf16.h>
#include <math.h>
#include <stdint.h>

#define B_   2
#define T_   2048
#define D_   2048
#define HQ_  16
#define HK_  4
#define HD_  128
#define MROWS (B_*T_)            // 4096
#define QELEMS (MROWS*HQ_*HD_)   // 8388608
#define KVELEMS (MROWS*HK_*HD_)  // 2097152

// fp32 scratch
__device__ float g_q[QELEMS];
__device__ float g_kraw[KVELEMS];
__device__ float g_vraw[KVELEMS];
__device__ float g_attn[QELEMS];
// bf16 split scratch
__device__ __nv_bfloat16 g_xs0[MROWS*D_];
__device__ __nv_bfloat16 g_xs1[MROWS*D_];
__device__ __nv_bfloat16 g_wqT0[D_*D_], g_wqT1[D_*D_];
__device__ __nv_bfloat16 g_wkT0[512*D_], g_wkT1[512*D_];
__device__ __nv_bfloat16 g_wvT0[512*D_], g_wvT1[512*D_];
__device__ __nv_bfloat16 g_woT0[D_*D_], g_woT1[D_*D_];

// ============================ helpers =========================================
__device__ __forceinline__ uint32_t smem_u32(const void* p) {
    uint32_t a;
    asm("{ .reg .u64 t; cvta.to.shared.u64 t, %1; cvt.u32.u64 %0, t; }" : "=r"(a) : "l"(p));
    return a;
}
__device__ __forceinline__ void cpasync16(uint32_t s, const void* g) {
    asm volatile("cp.async.cg.shared.global [%0], [%1], 16;" :: "r"(s), "l"(g));
}
__device__ __forceinline__ void ldsm4(uint32_t& r0, uint32_t& r1, uint32_t& r2, uint32_t& r3,
                                      uint32_t addr) {
    asm volatile("ldmatrix.sync.aligned.m8n8.x4.shared.b16 {%0,%1,%2,%3}, [%4];"
                 : "=r"(r0), "=r"(r1), "=r"(r2), "=r"(r3) : "r"(addr));
}
__device__ __forceinline__ void mma16816(float* c, const uint32_t* a, const uint32_t* b) {
    asm volatile("mma.sync.aligned.m16n8k16.row.col.f32.bf16.bf16.f32 "
                 "{%0,%1,%2,%3}, {%4,%5,%6,%7}, {%8,%9}, {%0,%1,%2,%3};"
                 : "+f"(c[0]), "+f"(c[1]), "+f"(c[2]), "+f"(c[3])
                 : "r"(a[0]), "r"(a[1]), "r"(a[2]), "r"(a[3]), "r"(b[0]), "r"(b[1]));
}
// swizzled byte offset within a [rows][32bf16] tile (64B rows, 16B chunks)
__device__ __forceinline__ uint32_t swadr(int row, int ch) {
    return (uint32_t)(row * 64 + ((ch ^ ((row >> 1) & 3)) << 4));
}

// ============================ split / transpose preps ==========================
__global__ void split_f32(const float* __restrict__ in, __nv_bfloat16* __restrict__ o0,
                          __nv_bfloat16* __restrict__ o1) {
    int i = blockIdx.x * 256 + threadIdx.x;
    float4 v = ((const float4*)in)[i];
    __nv_bfloat16 h[4], l[4];
    float vv[4] = {v.x, v.y, v.z, v.w};
    #pragma unroll
    for (int j = 0; j < 4; j++) {
        h[j] = __float2bfloat16(vv[j]);
        l[j] = __float2bfloat16(vv[j] - __bfloat162float(h[j]));
    }
    ((ushort4*)o0)[i] = make_ushort4(*(unsigned short*)&h[0], *(unsigned short*)&h[1],
                                     *(unsigned short*)&h[2], *(unsigned short*)&h[3]);
    ((ushort4*)o1)[i] = make_ushort4(*(unsigned short*)&l[0], *(unsigned short*)&l[1],
                                     *(unsigned short*)&l[2], *(unsigned short*)&l[3]);
}

// W [2048][N] fp32 -> Wt0/Wt1 [N][2048] bf16
__global__ void wsplitT(const float* __restrict__ W, __nv_bfloat16* __restrict__ t0,
                        __nv_bfloat16* __restrict__ t1, int N) {
    __shared__ float tile[32][33];
    int n0 = blockIdx.x * 32, k0 = blockIdx.y * 32;
    int tx = threadIdx.x, ty = threadIdx.y;
    #pragma unroll
    for (int i = 0; i < 4; i++)
        tile[ty + i * 8][tx] = W[(long)(k0 + ty + i * 8) * N + n0 + tx];
    __syncthreads();
    #pragma unroll
    for (int i = 0; i < 4; i++) {
        float v = tile[tx][ty + i * 8];
        __nv_bfloat16 h = __float2bfloat16(v);
        __nv_bfloat16 l = __float2bfloat16(v - __bfloat162float(h));
        long o = (long)(n0 + ty + i * 8) * 2048 + k0 + tx;
        t0[o] = h; t1[o] = l;
    }
}

// ============================ mma.sync bf16x3 GEMM =============================
// C[M,N] = A[M,2048] * B[2048,N]; A splits row-major [M][2048], B as Bt [N][2048].
// CTA tile 128x64, Kc=32, 2-stage cp.async pipeline.
#define STG_BYTES 24576
#define OFF_AH 0
#define OFF_AL 8192
#define OFF_BH 16384
#define OFF_BL 20480
#define GSM_TOT (2*STG_BYTES)   // 49152

__global__ void __launch_bounds__(256) gemm_mma(
    const __nv_bfloat16* __restrict__ A0, const __nv_bfloat16* __restrict__ A1,
    const __nv_bfloat16* __restrict__ B0, const __nv_bfloat16* __restrict__ B1,
    float* __restrict__ C, int N) {
    extern __shared__ char smem[];
    uint32_t sb = smem_u32(smem);
    int tid = threadIdx.x, lane = tid & 31, wid = tid >> 5;
    int wm = wid & 3, wn = wid >> 2;
    long m0 = (long)blockIdx.y * 128;
    int n0 = blockIdx.x * 64;

    // per-lane ldmatrix address components
    int lrow = lane & 7, ltile = lane >> 3;
    int a_row = wm * 32 + ((ltile & 1) << 3) + lrow;   // + mf*16
    int a_ch  = ltile >> 1;                            // + ks*2
    int b_row = wn * 32 + ((ltile >> 1) << 3) + lrow;  // + nf2*16
    int b_ch  = ltile & 1;                             // + ks*2

    float acc[2][4][4];
    #pragma unroll
    for (int mf = 0; mf < 2; mf++)
        #pragma unroll
        for (int nf = 0; nf < 4; nf++)
            #pragma unroll
            for (int j = 0; j < 4; j++) acc[mf][nf][j] = 0.f;

    // cp.async slot assignment
    int ar0 = tid >> 2, ach = tid & 3;       // A pass0 rows 0..63, pass1 +64
    int br  = tid >> 2, bch = tid & 3;       // B rows 0..63

    // issue one stage
    auto issue = [&](int st, int kc) {
        uint32_t base = sb + st * STG_BYTES;
        #pragma unroll
        for (int p = 0; p < 2; p++) {
            int r = ar0 + p * 64;
            uint32_t sw = swadr(r, ach);
            long g = (m0 + r) * 2048 + kc + ach * 8;
            cpasync16(base + OFF_AH + sw, A0 + g);
            cpasync16(base + OFF_AL + sw, A1 + g);
        }
        {
            uint32_t sw = swadr(br, bch);
            long g = (long)(n0 + br) * 2048 + kc + bch * 8;
            cpasync16(base + OFF_BH + sw, B0 + g);
            cpasync16(base + OFF_BL + sw, B1 + g);
        }
        asm volatile("cp.async.commit_group;" ::: "memory");
    };

    issue(0, 0);
    const int KI = 2048 / 32;
    for (int kci = 0; kci < KI; kci++) {
        if (kci + 1 < KI) {
            issue((kci + 1) & 1, (kci + 1) * 32);
            asm volatile("cp.async.wait_group 1;" ::: "memory");
        } else {
            asm volatile("cp.async.wait_group 0;" ::: "memory");
        }
        __syncthreads();

        uint32_t base = sb + (kci & 1) * STG_BYTES;
        #pragma unroll
        for (int ks = 0; ks < 2; ks++) {
            uint32_t ah[2][4], al[2][4];
            #pragma unroll
            for (int mf = 0; mf < 2; mf++) {
                uint32_t adr = base + OFF_AH + swadr(a_row + mf * 16, ks * 2 + a_ch);
                ldsm4(ah[mf][0], ah[mf][1], ah[mf][2], ah[mf][3], adr);
                adr = base + OFF_AL + swadr(a_row + mf * 16, ks * 2 + a_ch);
                ldsm4(al[mf][0], al[mf][1], al[mf][2], al[mf][3], adr);
            }
            uint32_t bh[4][2], bl[4][2];
            #pragma unroll
            for (int nf2 = 0; nf2 < 2; nf2++) {
                uint32_t adr = base + OFF_BH + swadr(b_row + nf2 * 16, ks * 2 + b_ch);
                ldsm4(bh[nf2*2][0], bh[nf2*2][1], bh[nf2*2+1][0], bh[nf2*2+1][1], adr);
                adr = base + OFF_BL + swadr(b_row + nf2 * 16, ks * 2 + b_ch);
                ldsm4(bl[nf2*2][0], bl[nf2*2][1], bl[nf2*2+1][0], bl[nf2*2+1][1], adr);
            }
            #pragma unroll
            for (int mf = 0; mf < 2; mf++)
                #pragma unroll
                for (int nf = 0; nf < 4; nf++) {
                    mma16816(acc[mf][nf], ah[mf], bh[nf]);
                    mma16816(acc[mf][nf], ah[mf], bl[nf]);
                    mma16816(acc[mf][nf], al[mf], bh[nf]);
                }
        }
        __syncthreads();
    }

    // epilogue
    int cr = lane >> 2, cc = (lane & 3) << 1;
    #pragma unroll
    for (int mf = 0; mf < 2; mf++)
        #pragma unroll
        for (int nf = 0; nf < 4; nf++) {
            long row = m0 + wm * 32 + mf * 16 + cr;
            int col = n0 + wn * 32 + nf * 8 + cc;
            *(float2*)(C + row * N + col)       = make_float2(acc[mf][nf][0], acc[mf][nf][1]);
            *(float2*)(C + (row + 8) * N + col) = make_float2(acc[mf][nf][2], acc[mf][nf][3]);
        }
}

// ============================ RoPE + pack ======================================
__global__ void rope_pack(float* __restrict__ q, const float* __restrict__ kraw,
                          const float* __restrict__ vraw, float* __restrict__ kv) {
    int idx = blockIdx.x * 256 + threadIdx.x;
    {
        int row = idx >> 10;
        int rem = idx & 1023;
        int h = rem >> 6, m = rem & 63;
        int t = row & (T_ - 1);
        float invf = powf(10000.0f, -(float)(2 * m) * (1.0f / 128.0f));
        float ang = (float)t * invf;
        float c = cosf(ang), s = sinf(ang);
        const float scale = 0.08838834764831845f;
        long base = (long)row * (HQ_ * HD_) + h * HD_ + m;
        float x1 = q[base], x2 = q[base + 64];
        q[base]      = (x1 * c - x2 * s) * scale;
        q[base + 64] = (x2 * c + x1 * s) * scale;
    }
    if (idx < MROWS * HK_ * 64) {
        int krow = idx >> 8;
        int krem = idx & 255;
        int kh = krem >> 6, km = krem & 63;
        int kt = krow & (T_ - 1);
        float invf = powf(10000.0f, -(float)(2 * km) * (1.0f / 128.0f));
        float ang = (float)kt * invf;
        float c = cosf(ang), s = sinf(ang);
        long src = (long)krow * (HK_ * HD_) + kh * HD_ + km;
        float x1 = kraw[src], x2 = kraw[src + 64];
        long dst = ((long)krow * HK_ + kh) * 256 + km;
        kv[dst]      = x1 * c - x2 * s;
        kv[dst + 64] = x2 * c + x1 * s;
    }
    if (idx < KVELEMS / 4) {
        int f = idx;
        int vrow = f >> 7;
        int vc4 = f & 127;
        int vh = vc4 >> 5, vd4 = (vc4 & 31) << 2;
        float4 v = *(const float4*)(vraw + (long)f * 4);
        long dst = ((long)vrow * HK_ + vh) * 256 + 128 + vd4;
        *(float4*)(kv + dst) = v;
    }
}

// ============================ threefry (partitionable) =========================
__device__ __forceinline__ unsigned tf_rotl(unsigned x, int r) {
    return (x << r) | (x >> (32 - r));
}
__device__ __forceinline__ float dropout_keep(unsigned e) {
    unsigned x0 = 0u, x1 = e;
    const unsigned k0 = 0u, k1 = 1u, k2 = 0x1BD11BDAu ^ k0 ^ k1;
    x0 += k0; x1 += k1;
#define TFR(r) { x0 += x1; x1 = tf_rotl(x1, r); x1 ^= x0; }
    TFR(13) TFR(15) TFR(26) TFR(6)
    x0 += k1; x1 += k2 + 1u;
    TFR(17) TFR(29) TFR(16) TFR(24)
    x0 += k2; x1 += k0 + 2u;
    TFR(13) TFR(15) TFR(26) TFR(6)
    x0 += k0; x1 += k1 + 3u;
    TFR(17) TFR(29) TFR(16) TFR(24)
    x0 += k1; x1 += k2 + 4u;
    TFR(13) TFR(15) TFR(26) TFR(6)
    x0 += k2; x1 += k0 + 5u;
#undef TFR
    unsigned bits = x0 ^ x1;
    float u = __uint_as_float((bits >> 9) | 0x3F800000u) - 1.0f;
    return (u < 0.9f) ? (1.0f / 0.9f) : 0.0f;
}

// ============================ attention ========================================
#define ATT_SMEM_FLOATS (128*68 + 128*68 + 64*128 + 64*64)
__global__ void attn_kernel(const float* __restrict__ Q, const float* __restrict__ KV,
                            float* __restrict__ O) {
    extern __shared__ float sm[];
    float* Qts = sm;
    float* Kts = sm + 128 * 68;
    float* Vs  = Kts + 128 * 68;
    float* Pts = Vs + 64 * 128;

    int tid = threadIdx.x;
    int ty = tid >> 4, tx = tid & 15;
    int qb = (gridDim.x - 1) - blockIdx.x;
    int bh = blockIdx.y;
    int b = bh >> 4, hq = bh & 15;
    int hk = hq & 3;

    #pragma unroll
    for (int l = 0; l < 8; l++) {
        int lin = tid + (l << 8);
        int r = lin & 63;
        int d4 = (lin >> 6) << 2;
        const float* src = Q + (long)(b * T_ + qb * 64 + r) * (HQ_ * HD_) + hq * HD_ + d4;
        float4 v = *(const float4*)src;
        float* dst = Qts + d4 * 68 + r;
        dst[0] = v.x; dst[68] = v.y; dst[136] = v.z; dst[204] = v.w;
    }

    float m_i[4], l_i[4], o[4][8];
    #pragma unroll
    for (int r = 0; r < 4; r++) {
        m_i[r] = -INFINITY; l_i[r] = 0.f;
        #pragma unroll
        for (int c = 0; c < 8; c++) o[r][c] = 0.f;
    }
    unsigned ebase = (unsigned)(b * 16 + hq) * 4194304u;

    for (int jb = 0; jb <= qb; jb++) {
        #pragma unroll
        for (int l = 0; l < 8; l++) {
            int lin = tid + (l << 8);
            int r = lin & 63;
            int d4 = (lin >> 6) << 2;
            const float* ksrc = KV + ((long)(b * T_ + jb * 64 + r) * HK_ + hk) * 256 + d4;
            float4 v = *(const float4*)ksrc;
            float* dst = Kts + d4 * 68 + r;
            dst[0] = v.x; dst[68] = v.y; dst[136] = v.z; dst[204] = v.w;
            int r2 = lin >> 5;
            int e4 = (lin & 31) << 2;
            const float* vsrc = KV + ((long)(b * T_ + jb * 64 + r2) * HK_ + hk) * 256 + 128 + e4;
            *(float4*)(Vs + r2 * 128 + e4) = *(const float4*)vsrc;
        }
        __syncthreads();

        float s[4][4];
        #pragma unroll
        for (int r = 0; r < 4; r++)
            #pragma unroll
            for (int c = 0; c < 4; c++) s[r][c] = 0.f;
        #pragma unroll 8
        for (int d = 0; d < 128; d++) {
            float4 a  = *(const float4*)(Qts + d * 68 + (ty << 2));
            float4 bq = *(const float4*)(Kts + d * 68 + (tx << 2));
            float aa[4] = {a.x, a.y, a.z, a.w};
            float bb[4] = {bq.x, bq.y, bq.z, bq.w};
            #pragma unroll
            for (int r = 0; r < 4; r++)
                #pragma unroll
                for (int c = 0; c < 4; c++) s[r][c] += aa[r] * bb[c];
        }
        if (jb == qb) {
            #pragma unroll
            for (int r = 0; r < 4; r++)
                #pragma unroll
                for (int c = 0; c < 4; c++)
                    if ((tx << 2) + c > (ty << 2) + r) s[r][c] = -1e30f;
        }

        #pragma unroll
        for (int r = 0; r < 4; r++) {
            float rm = fmaxf(fmaxf(s[r][0], s[r][1]), fmaxf(s[r][2], s[r][3]));
            #pragma unroll
            for (int off = 8; off; off >>= 1)
                rm = fmaxf(rm, __shfl_xor_sync(0xffffffffu, rm, off, 16));
            float mnew = fmaxf(m_i[r], rm);
            float corr = expf(m_i[r] - mnew);
            float p[4], rs = 0.f;
            #pragma unroll
            for (int c = 0; c < 4; c++) { p[c] = expf(s[r][c] - mnew); rs += p[c]; }
            #pragma unroll
            for (int off = 8; off; off >>= 1)
                rs += __shfl_xor_sync(0xffffffffu, rs, off, 16);
            l_i[r] = l_i[r] * corr + rs;
            m_i[r] = mnew;
            #pragma unroll
            for (int c = 0; c < 8; c++) o[r][c] *= corr;

            unsigned ig = (unsigned)(qb * 64 + (ty << 2) + r);
            unsigned jg0 = (unsigned)(jb * 64 + (tx << 2));
            int i = (ty << 2) + r;
            #pragma unroll
            for (int c = 0; c < 4; c++) {
                float pd = p[c] * dropout_keep(ebase + ig * 2048u + jg0 + (unsigned)c);
                int j = (tx << 2) + c;
                Pts[j * 64 + (((i >> 2) ^ (j & 15)) << 2) + (i & 3)] = pd;
            }
        }
        __syncthreads();

        #pragma unroll 4
        for (int j = 0; j < 64; j++) {
            float4 a  = *(const float4*)(Pts + j * 64 + ((ty ^ (j & 15)) << 2));
            float4 b1 = *(const float4*)(Vs + j * 128 + (tx << 2));
            float4 b2 = *(const float4*)(Vs + j * 128 + 64 + (tx << 2));
            float aa[4] = {a.x, a.y, a.z, a.w};
            float bb[8] = {b1.x, b1.y, b1.z, b1.w, b2.x, b2.y, b2.z, b2.w};
            #pragma unroll
            for (int r = 0; r < 4; r++)
                #pragma unroll
                for (int c = 0; c < 8; c++) o[r][c] += aa[r] * bb[c];
        }
        __syncthreads();
    }

    #pragma unroll
    for (int r = 0; r < 4; r++) {
        float inv = 1.0f / l_i[r];
        long base = (long)(b * T_ + qb * 64 + (ty << 2) + r) * (HQ_ * HD_) + hq * HD_;
        float4 o1 = make_float4(o[r][0] * inv, o[r][1] * inv, o[r][2] * inv, o[r][3] * inv);
        float4 o2 = make_float4(o[r][4] * inv, o[r][5] * inv, o[r][6] * inv, o[r][7] * inv);
        *(float4*)(O + base + (tx << 2)) = o1;
        *(float4*)(O + base + 64 + (tx << 2)) = o2;
    }
}

// ============================ launch ===========================================
extern "C" void kernel_launch(void* const* d_in, const int* in_sizes, int n_in,
                              void* d_out, int out_size) {
    const float* x  = (const float*)d_in[0];
    const float* wq = (const float*)d_in[1];
    const float* wk = (const float*)d_in[2];
    const float* wv = (const float*)d_in[3];
    const float* wo = (const float*)d_in[4];
    float* out = (float*)d_out;
    float* kv  = out + QELEMS;

    float *qp, *kp, *vp, *ap;
    cudaGetSymbolAddress((void**)&qp, g_q);
    cudaGetSymbolAddress((void**)&kp, g_kraw);
    cudaGetSymbolAddress((void**)&vp, g_vraw);
    cudaGetSymbolAddress((void**)&ap, g_attn);
    __nv_bfloat16 *xs0, *xs1, *wqT0, *wqT1, *wkT0, *wkT1, *wvT0, *wvT1, *woT0, *woT1;
    cudaGetSymbolAddress((void**)&xs0, g_xs0);
    cudaGetSymbolAddress((void**)&xs1, g_xs1);
    cudaGetSymbolAddress((void**)&wqT0, g_wqT0);
    cudaGetSymbolAddress((void**)&wqT1, g_wqT1);
    cudaGetSymbolAddress((void**)&wkT0, g_wkT0);
    cudaGetSymbolAddress((void**)&wkT1, g_wkT1);
    cudaGetSymbolAddress((void**)&wvT0, g_wvT0);
    cudaGetSymbolAddress((void**)&wvT1, g_wvT1);
    cudaGetSymbolAddress((void**)&woT0, g_woT0);
    cudaGetSymbolAddress((void**)&woT1, g_woT1);

    cudaFuncSetAttribute(gemm_mma, cudaFuncAttributeMaxDynamicSharedMemorySize, GSM_TOT);

    // prep
    split_f32<<<(MROWS * D_ / 4) / 256, 256>>>(x, xs0, xs1);
    wsplitT<<<dim3(D_ / 32, D_ / 32), dim3(32, 8)>>>(wq, wqT0, wqT1, D_);
    wsplitT<<<dim3(512 / 32, D_ / 32), dim3(32, 8)>>>(wk, wkT0, wkT1, 512);
    wsplitT<<<dim3(512 / 32, D_ / 32), dim3(32, 8)>>>(wv, wvT0, wvT1, 512);
    wsplitT<<<dim3(D_ / 32, D_ / 32), dim3(32, 8)>>>(wo, woT0, woT1, D_);

    // projections (tensor pipe)
    gemm_mma<<<dim3(D_ / 64, MROWS / 128), 256, GSM_TOT>>>(xs0, xs1, wqT0, wqT1, qp, D_);
    gemm_mma<<<dim3(512 / 64, MROWS / 128), 256, GSM_TOT>>>(xs0, xs1, wkT0, wkT1, kp, 512);
    gemm_mma<<<dim3(512 / 64, MROWS / 128), 256, GSM_TOT>>>(xs0, xs1, wvT0, wvT1, vp, 512);

    rope_pack<<<(MROWS * HQ_ * 64) / 256, 256>>>(qp, kp, vp, kv);

    int smem = ATT_SMEM_FLOATS * 4;
    cudaFuncSetAttribute(attn_kernel, cudaFuncAttributeMaxDynamicSharedMemorySize, smem);
    attn_kernel<<<dim3(T_ / 64, B_ * HQ_), 256, smem>>>(qp, kv, ap);

    // out projection
    split_f32<<<(MROWS * D_ / 4) / 256, 256>>>(ap, xs0, xs1);
    gemm_mma<<<dim3(D_ / 64, MROWS / 128), 256, GSM_TOT>>>(xs0, xs1, woT0, woT1, out, D_);
}

// round 5
// speedup vs baseline: 2.6958x; 1.5410x over previous
#include <cuda_runtime.h>
#include <cuda_bf16.h>
#include <math.h>
#include <stdint.h>

#define B_   2
#define T_   2048
#define D_   2048
#define HQ_  16
#define HK_  4
#define HD_  128
#define MROWS (B_*T_)            // 4096
#define QELEMS (MROWS*HQ_*HD_)   // 8388608
#define KVELEMS (MROWS*HK_*HD_)  // 2097152

// fp32 scratch
__device__ float g_q[QELEMS];
__device__ float g_kraw[KVELEMS];
__device__ float g_vraw[KVELEMS];
__device__ float g_attn[QELEMS];
// bf16 split scratch (GEMM)
__device__ __nv_bfloat16 g_xs0[MROWS*D_];
__device__ __nv_bfloat16 g_xs1[MROWS*D_];
__device__ __nv_bfloat16 g_wqT0[D_*D_], g_wqT1[D_*D_];
__device__ __nv_bfloat16 g_wkT0[512*D_], g_wkT1[512*D_];
__device__ __nv_bfloat16 g_wvT0[512*D_], g_wvT1[512*D_];
__device__ __nv_bfloat16 g_woT0[D_*D_], g_woT1[D_*D_];
// bf16 split scratch (attention), head-major [b][h][t][128]
__device__ __nv_bfloat16 g_aqh[QELEMS], g_aql[QELEMS];
__device__ __nv_bfloat16 g_akh[KVELEMS], g_akl[KVELEMS];
__device__ __nv_bfloat16 g_avh[KVELEMS], g_avl[KVELEMS];

// ============================ helpers =========================================
__device__ __forceinline__ uint32_t smem_u32(const void* p) {
    uint32_t a;
    asm("{ .reg .u64 t; cvta.to.shared.u64 t, %1; cvt.u32.u64 %0, t; }" : "=r"(a) : "l"(p));
    return a;
}
__device__ __forceinline__ void cpasync16(uint32_t s, const void* g) {
    asm volatile("cp.async.cg.shared.global [%0], [%1], 16;" :: "r"(s), "l"(g));
}
__device__ __forceinline__ void ldsm4(uint32_t& r0, uint32_t& r1, uint32_t& r2, uint32_t& r3,
                                      uint32_t addr) {
    asm volatile("ldmatrix.sync.aligned.m8n8.x4.shared.b16 {%0,%1,%2,%3}, [%4];"
                 : "=r"(r0), "=r"(r1), "=r"(r2), "=r"(r3) : "r"(addr));
}
__device__ __forceinline__ void ldsm4t(uint32_t& r0, uint32_t& r1, uint32_t& r2, uint32_t& r3,
                                       uint32_t addr) {
    asm volatile("ldmatrix.sync.aligned.m8n8.x4.trans.shared.b16 {%0,%1,%2,%3}, [%4];"
                 : "=r"(r0), "=r"(r1), "=r"(r2), "=r"(r3) : "r"(addr));
}
__device__ __forceinline__ void mma16816(float* c, const uint32_t* a, const uint32_t* b) {
    asm volatile("mma.sync.aligned.m16n8k16.row.col.f32.bf16.bf16.f32 "
                 "{%0,%1,%2,%3}, {%4,%5,%6,%7}, {%8,%9}, {%0,%1,%2,%3};"
                 : "+f"(c[0]), "+f"(c[1]), "+f"(c[2]), "+f"(c[3])
                 : "r"(a[0]), "r"(a[1]), "r"(a[2]), "r"(a[3]), "r"(b[0]), "r"(b[1]));
}
// GEMM tile swizzle: [rows][32 bf16] (64B rows, 16B chunks)
__device__ __forceinline__ uint32_t swadr(int row, int ch) {
    return (uint32_t)(row * 64 + ((ch ^ ((row >> 1) & 3)) << 4));
}
// attention tile swizzle: [rows][128 bf16] (256B rows, 16 chunks of 16B)
__device__ __forceinline__ uint32_t asw(int row, int ch) {
    return (uint32_t)(row * 256 + ((ch ^ (row & 7)) << 4));
}

// ============================ split / transpose preps ==========================
__global__ void split_f32(const float* __restrict__ in, __nv_bfloat16* __restrict__ o0,
                          __nv_bfloat16* __restrict__ o1) {
    int i = blockIdx.x * 256 + threadIdx.x;
    float4 v = ((const float4*)in)[i];
    __nv_bfloat16 h[4], l[4];
    float vv[4] = {v.x, v.y, v.z, v.w};
    #pragma unroll
    for (int j = 0; j < 4; j++) {
        h[j] = __float2bfloat16(vv[j]);
        l[j] = __float2bfloat16(vv[j] - __bfloat162float(h[j]));
    }
    ((ushort4*)o0)[i] = make_ushort4(*(unsigned short*)&h[0], *(unsigned short*)&h[1],
                                     *(unsigned short*)&h[2], *(unsigned short*)&h[3]);
    ((ushort4*)o1)[i] = make_ushort4(*(unsigned short*)&l[0], *(unsigned short*)&l[1],
                                     *(unsigned short*)&l[2], *(unsigned short*)&l[3]);
}

__global__ void wsplitT(const float* __restrict__ W, __nv_bfloat16* __restrict__ t0,
                        __nv_bfloat16* __restrict__ t1, int N) {
    __shared__ float tile[32][33];
    int n0 = blockIdx.x * 32, k0 = blockIdx.y * 32;
    int tx = threadIdx.x, ty = threadIdx.y;
    #pragma unroll
    for (int i = 0; i < 4; i++)
        tile[ty + i * 8][tx] = W[(long)(k0 + ty + i * 8) * N + n0 + tx];
    __syncthreads();
    #pragma unroll
    for (int i = 0; i < 4; i++) {
        float v = tile[tx][ty + i * 8];
        __nv_bfloat16 h = __float2bfloat16(v);
        __nv_bfloat16 l = __float2bfloat16(v - __bfloat162float(h));
        long o = (long)(n0 + ty + i * 8) * 2048 + k0 + tx;
        t0[o] = h; t1[o] = l;
    }
}

// ============================ mma.sync bf16x3 GEMM (unchanged) =================
#define STG_BYTES 24576
#define OFF_AH 0
#define OFF_AL 8192
#define OFF_BH 16384
#define OFF_BL 20480
#define GSM_TOT (2*STG_BYTES)

__global__ void __launch_bounds__(256) gemm_mma(
    const __nv_bfloat16* __restrict__ A0, const __nv_bfloat16* __restrict__ A1,
    const __nv_bfloat16* __restrict__ B0, const __nv_bfloat16* __restrict__ B1,
    float* __restrict__ C, int N) {
    extern __shared__ char smem[];
    uint32_t sb = smem_u32(smem);
    int tid = threadIdx.x, lane = tid & 31, wid = tid >> 5;
    int wm = wid & 3, wn = wid >> 2;
    long m0 = (long)blockIdx.y * 128;
    int n0 = blockIdx.x * 64;

    int lrow = lane & 7, ltile = lane >> 3;
    int a_row = wm * 32 + ((ltile & 1) << 3) + lrow;
    int a_ch  = ltile >> 1;
    int b_row = wn * 32 + ((ltile >> 1) << 3) + lrow;
    int b_ch  = ltile & 1;

    float acc[2][4][4];
    #pragma unroll
    for (int mf = 0; mf < 2; mf++)
        #pragma unroll
        for (int nf = 0; nf < 4; nf++)
            #pragma unroll
            for (int j = 0; j < 4; j++) acc[mf][nf][j] = 0.f;

    int ar0 = tid >> 2, ach = tid & 3;
    int br  = tid >> 2, bch = tid & 3;

    auto issue = [&](int st, int kc) {
        uint32_t base = sb + st * STG_BYTES;
        #pragma unroll
        for (int p = 0; p < 2; p++) {
            int r = ar0 + p * 64;
            uint32_t sw = swadr(r, ach);
            long g = (m0 + r) * 2048 + kc + ach * 8;
            cpasync16(base + OFF_AH + sw, A0 + g);
            cpasync16(base + OFF_AL + sw, A1 + g);
        }
        {
            uint32_t sw = swadr(br, bch);
            long g = (long)(n0 + br) * 2048 + kc + bch * 8;
            cpasync16(base + OFF_BH + sw, B0 + g);
            cpasync16(base + OFF_BL + sw, B1 + g);
        }
        asm volatile("cp.async.commit_group;" ::: "memory");
    };

    issue(0, 0);
    const int KI = 2048 / 32;
    for (int kci = 0; kci < KI; kci++) {
        if (kci + 1 < KI) {
            issue((kci + 1) & 1, (kci + 1) * 32);
            asm volatile("cp.async.wait_group 1;" ::: "memory");
        } else {
            asm volatile("cp.async.wait_group 0;" ::: "memory");
        }
        __syncthreads();

        uint32_t base = sb + (kci & 1) * STG_BYTES;
        #pragma unroll
        for (int ks = 0; ks < 2; ks++) {
            uint32_t ah[2][4], al[2][4];
            #pragma unroll
            for (int mf = 0; mf < 2; mf++) {
                uint32_t adr = base + OFF_AH + swadr(a_row + mf * 16, ks * 2 + a_ch);
                ldsm4(ah[mf][0], ah[mf][1], ah[mf][2], ah[mf][3], adr);
                adr = base + OFF_AL + swadr(a_row + mf * 16, ks * 2 + a_ch);
                ldsm4(al[mf][0], al[mf][1], al[mf][2], al[mf][3], adr);
            }
            uint32_t bh[4][2], bl[4][2];
            #pragma unroll
            for (int nf2 = 0; nf2 < 2; nf2++) {
                uint32_t adr = base + OFF_BH + swadr(b_row + nf2 * 16, ks * 2 + b_ch);
                ldsm4(bh[nf2*2][0], bh[nf2*2][1], bh[nf2*2+1][0], bh[nf2*2+1][1], adr);
                adr = base + OFF_BL + swadr(b_row + nf2 * 16, ks * 2 + b_ch);
                ldsm4(bl[nf2*2][0], bl[nf2*2][1], bl[nf2*2+1][0], bl[nf2*2+1][1], adr);
            }
            #pragma unroll
            for (int mf = 0; mf < 2; mf++)
                #pragma unroll
                for (int nf = 0; nf < 4; nf++) {
                    mma16816(acc[mf][nf], ah[mf], bh[nf]);
                    mma16816(acc[mf][nf], ah[mf], bl[nf]);
                    mma16816(acc[mf][nf], al[mf], bh[nf]);
                }
        }
        __syncthreads();
    }

    int cr = lane >> 2, cc = (lane & 3) << 1;
    #pragma unroll
    for (int mf = 0; mf < 2; mf++)
        #pragma unroll
        for (int nf = 0; nf < 4; nf++) {
            long row = m0 + wm * 32 + mf * 16 + cr;
            int col = n0 + wn * 32 + nf * 8 + cc;
            *(float2*)(C + row * N + col)       = make_float2(acc[mf][nf][0], acc[mf][nf][1]);
            *(float2*)(C + (row + 8) * N + col) = make_float2(acc[mf][nf][2], acc[mf][nf][3]);
        }
}

// ============================ RoPE + pack + bf16 splits ========================
__global__ void rope_pack(const float* __restrict__ q, const float* __restrict__ kraw,
                          const float* __restrict__ vraw, float* __restrict__ kv,
                          __nv_bfloat16* __restrict__ qh, __nv_bfloat16* __restrict__ ql,
                          __nv_bfloat16* __restrict__ kh, __nv_bfloat16* __restrict__ kl,
                          __nv_bfloat16* __restrict__ vh, __nv_bfloat16* __restrict__ vl) {
    int idx = blockIdx.x * 256 + threadIdx.x;
    {
        int row = idx >> 10;          // b*T + t
        int rem = idx & 1023;
        int h = rem >> 6, m = rem & 63;
        int b = row >> 11, t = row & 2047;
        float invf = powf(10000.0f, -(float)(2 * m) * (1.0f / 128.0f));
        float ang = (float)t * invf;
        float c = cosf(ang), s = sinf(ang);
        const float scale = 0.08838834764831845f;
        long base = (long)row * (HQ_ * HD_) + h * HD_ + m;
        float x1 = q[base], x2 = q[base + 64];
        float v1 = (x1 * c - x2 * s) * scale;
        float v2 = (x2 * c + x1 * s) * scale;
        long so = ((long)(b * HQ_ + h) * T_ + t) * 128 + m;
        __nv_bfloat16 h1 = __float2bfloat16(v1), h2 = __float2bfloat16(v2);
        qh[so] = h1;      qh[so + 64] = h2;
        ql[so] = __float2bfloat16(v1 - __bfloat162float(h1));
        ql[so + 64] = __float2bfloat16(v2 - __bfloat162float(h2));
    }
    if (idx < MROWS * HK_ * 64) {
        int krow = idx >> 8;
        int krem = idx & 255;
        int khd = krem >> 6, km = krem & 63;
        int b = krow >> 11, t = krow & 2047;
        float invf = powf(10000.0f, -(float)(2 * km) * (1.0f / 128.0f));
        float ang = (float)t * invf;
        float c = cosf(ang), s = sinf(ang);
        long src = (long)krow * (HK_ * HD_) + khd * HD_ + km;
        float x1 = kraw[src], x2 = kraw[src + 64];
        float v1 = x1 * c - x2 * s;
        float v2 = x2 * c + x1 * s;
        long dst = ((long)krow * HK_ + khd) * 256 + km;
        kv[dst]      = v1;
        kv[dst + 64] = v2;
        long so = ((long)(b * HK_ + khd) * T_ + t) * 128 + km;
        __nv_bfloat16 h1 = __float2bfloat16(v1), h2 = __float2bfloat16(v2);
        kh[so] = h1;      kh[so + 64] = h2;
        kl[so] = __float2bfloat16(v1 - __bfloat162float(h1));
        kl[so + 64] = __float2bfloat16(v2 - __bfloat162float(h2));
    }
    if (idx < KVELEMS / 4) {
        int f = idx;
        int vrow = f >> 7;
        int vc4 = f & 127;
        int vhd = vc4 >> 5, vd4 = (vc4 & 31) << 2;
        int b = vrow >> 11, t = vrow & 2047;
        float4 v = *(const float4*)(vraw + (long)f * 4);
        long dst = ((long)vrow * HK_ + vhd) * 256 + 128 + vd4;
        *(float4*)(kv + dst) = v;
        long so = ((long)(b * HK_ + vhd) * T_ + t) * 128 + vd4;
        float vv[4] = {v.x, v.y, v.z, v.w};
        #pragma unroll
        for (int j = 0; j < 4; j++) {
            __nv_bfloat16 hj = __float2bfloat16(vv[j]);
            vh[so + j] = hj;
            vl[so + j] = __float2bfloat16(vv[j] - __bfloat162float(hj));
        }
    }
}

// ============================ threefry (partitionable) =========================
__device__ __forceinline__ unsigned tf_rotl(unsigned x, int r) {
    return (x << r) | (x >> (32 - r));
}
__device__ __forceinline__ float dropout_keep(unsigned e) {
    unsigned x0 = 0u, x1 = e;
    const unsigned k0 = 0u, k1 = 1u, k2 = 0x1BD11BDAu ^ k0 ^ k1;
    x0 += k0; x1 += k1;
#define TFR(r) { x0 += x1; x1 = tf_rotl(x1, r); x1 ^= x0; }
    TFR(13) TFR(15) TFR(26) TFR(6)
    x0 += k1; x1 += k2 + 1u;
    TFR(17) TFR(29) TFR(16) TFR(24)
    x0 += k2; x1 += k0 + 2u;
    TFR(13) TFR(15) TFR(26) TFR(6)
    x0 += k0; x1 += k1 + 3u;
    TFR(17) TFR(29) TFR(16) TFR(24)
    x0 += k1; x1 += k2 + 4u;
    TFR(13) TFR(15) TFR(26) TFR(6)
    x0 += k2; x1 += k0 + 5u;
#undef TFR
    unsigned bits = x0 ^ x1;
    float u = __uint_as_float((bits >> 9) | 0x3F800000u) - 1.0f;
    return (u < 0.9f) ? (1.0f / 0.9f) : 0.0f;
}

// ============================ tensor-core attention ============================
// CTA: 128 q-rows x 64-kv blocks; 8 warps, each 16 q-rows. bf16x3 HMMA.
#define A_QH 0
#define A_QL (A_QH + 128*256)
#define A_KH (A_QL + 128*256)
#define A_KL (A_KH + 64*256)
#define A_VH (A_KL + 64*256)
#define A_VL (A_VH + 64*256)
#define A_TOT (A_VL + 64*256)    // 131072 bytes

__global__ void __launch_bounds__(256) attn_mma(
    const __nv_bfloat16* __restrict__ Qh, const __nv_bfloat16* __restrict__ Ql,
    const __nv_bfloat16* __restrict__ Kh, const __nv_bfloat16* __restrict__ Kl,
    const __nv_bfloat16* __restrict__ Vh, const __nv_bfloat16* __restrict__ Vl,
    float* __restrict__ O) {
    extern __shared__ char smem[];
    uint32_t sb = smem_u32(smem);
    int tid = threadIdx.x, lane = tid & 31, wid = tid >> 5;
    int qb = (gridDim.x - 1) - blockIdx.x;       // heavy blocks first
    int bh = blockIdx.y;
    int b = bh >> 4, hq = bh & 15, hk = hq & 3;

    const __nv_bfloat16* qhp = Qh + ((long)(b * HQ_ + hq) * T_ + qb * 128) * 128;
    const __nv_bfloat16* qlp = Ql + ((long)(b * HQ_ + hq) * T_ + qb * 128) * 128;
    const __nv_bfloat16* khp = Kh + (long)(b * HK_ + hk) * T_ * 128;
    const __nv_bfloat16* klp = Kl + (long)(b * HK_ + hk) * T_ * 128;
    const __nv_bfloat16* vhp = Vh + (long)(b * HK_ + hk) * T_ * 128;
    const __nv_bfloat16* vlp = Vl + (long)(b * HK_ + hk) * T_ * 128;

    // Q tiles: 2048 chunks x 2 arrays
    #pragma unroll
    for (int it = 0; it < 16; it++) {
        int lin = tid + it * 256;
        int arr = lin >> 11, cidx = lin & 2047;
        int row = cidx >> 4, ch = cidx & 15;
        const __nv_bfloat16* src = (arr ? qlp : qhp) + row * 128 + ch * 8;
        cpasync16(sb + (arr ? A_QL : A_QH) + asw(row, ch), src);
    }

    int qrw = wid * 16;                          // warp q-row base in tile
    float m1 = -INFINITY, m2 = -INFINITY, l1 = 0.f, l2 = 0.f;
    float o[16][4];
    #pragma unroll
    for (int nf = 0; nf < 16; nf++)
        #pragma unroll
        for (int c = 0; c < 4; c++) o[nf][c] = 0.f;

    unsigned ebase = (unsigned)(b * 16 + hq) * 4194304u;
    int ig1 = qb * 128 + qrw + (lane >> 2);      // global row (r1); r2 = +8

    // per-lane ldmatrix coords
    int a_row = qrw + ((lane >> 3) & 1) * 8 + (lane & 7);
    int a_chb = lane >> 4;
    int k_row8 = ((lane >> 4)) * 8 + (lane & 7);
    int k_chb = (lane >> 3) & 1;
    int v_row8 = ((lane >> 3) & 1) * 8 + (lane & 7);
    int v_chb = lane >> 4;

    int njb = 2 * qb + 2;
    for (int jb = 0; jb < njb; jb++) {
        // K/V tiles: 1024 chunks x 4 arrays
        #pragma unroll
        for (int it = 0; it < 16; it++) {
            int lin = tid + it * 256;
            int arr = lin >> 10, cidx = lin & 1023;
            int row = cidx >> 4, ch = cidx & 15;
            long g = (long)(jb * 64 + row) * 128 + ch * 8;
            const __nv_bfloat16* src = (arr == 0 ? khp : arr == 1 ? klp : arr == 2 ? vhp : vlp) + g;
            cpasync16(sb + A_KH + arr * 16384 + asw(row, ch), src);
        }
        asm volatile("cp.async.commit_group;" ::: "memory");
        asm volatile("cp.async.wait_group 0;" ::: "memory");
        __syncthreads();

        // S = Q K^T (bf16x3)
        float sc[8][4];
        #pragma unroll
        for (int nf = 0; nf < 8; nf++)
            #pragma unroll
            for (int c = 0; c < 4; c++) sc[nf][c] = 0.f;
        #pragma unroll
        for (int ks = 0; ks < 8; ks++) {
            uint32_t qh4[4], ql4[4];
            ldsm4(qh4[0], qh4[1], qh4[2], qh4[3], sb + A_QH + asw(a_row, 2 * ks + a_chb));
            ldsm4(ql4[0], ql4[1], ql4[2], ql4[3], sb + A_QL + asw(a_row, 2 * ks + a_chb));
            #pragma unroll
            for (int nfp = 0; nfp < 4; nfp++) {
                uint32_t kh4[4], kl4[4];
                int br = nfp * 16 + k_row8;
                int bc = 2 * ks + k_chb;
                ldsm4(kh4[0], kh4[1], kh4[2], kh4[3], sb + A_KH + asw(br, bc));
                ldsm4(kl4[0], kl4[1], kl4[2], kl4[3], sb + A_KL + asw(br, bc));
                mma16816(sc[2 * nfp],     qh4, kh4);
                mma16816(sc[2 * nfp],     qh4, kl4);
                mma16816(sc[2 * nfp],     ql4, kh4);
                mma16816(sc[2 * nfp + 1], qh4, kh4 + 2);
                mma16816(sc[2 * nfp + 1], qh4, kl4 + 2);
                mma16816(sc[2 * nfp + 1], ql4, kh4 + 2);
            }
        }

        // causal mask (only near diagonal)
        if (jb * 64 + 63 > qb * 128 + qrw) {
            #pragma unroll
            for (int nf = 0; nf < 8; nf++) {
                int j0 = jb * 64 + nf * 8 + (lane & 3) * 2;
                if (j0 > ig1)     sc[nf][0] = -INFINITY;
                if (j0 + 1 > ig1) sc[nf][1] = -INFINITY;
                if (j0 > ig1 + 8)     sc[nf][2] = -INFINITY;
                if (j0 + 1 > ig1 + 8) sc[nf][3] = -INFINITY;
            }
        }

        // online softmax (rows r1, r2)
        float mx1 = -INFINITY, mx2 = -INFINITY;
        #pragma unroll
        for (int nf = 0; nf < 8; nf++) {
            mx1 = fmaxf(mx1, fmaxf(sc[nf][0], sc[nf][1]));
            mx2 = fmaxf(mx2, fmaxf(sc[nf][2], sc[nf][3]));
        }
        mx1 = fmaxf(mx1, __shfl_xor_sync(0xffffffffu, mx1, 1));
        mx1 = fmaxf(mx1, __shfl_xor_sync(0xffffffffu, mx1, 2));
        mx2 = fmaxf(mx2, __shfl_xor_sync(0xffffffffu, mx2, 1));
        mx2 = fmaxf(mx2, __shfl_xor_sync(0xffffffffu, mx2, 2));
        float mn1 = fmaxf(m1, mx1), mn2 = fmaxf(m2, mx2);
        float cr1 = expf(m1 - mn1), cr2 = expf(m2 - mn2);
        float rs1 = 0.f, rs2 = 0.f;
        #pragma unroll
        for (int nf = 0; nf < 8; nf++) {
            sc[nf][0] = expf(sc[nf][0] - mn1); rs1 += sc[nf][0];
            sc[nf][1] = expf(sc[nf][1] - mn1); rs1 += sc[nf][1];
            sc[nf][2] = expf(sc[nf][2] - mn2); rs2 += sc[nf][2];
            sc[nf][3] = expf(sc[nf][3] - mn2); rs2 += sc[nf][3];
        }
        rs1 += __shfl_xor_sync(0xffffffffu, rs1, 1);
        rs1 += __shfl_xor_sync(0xffffffffu, rs1, 2);
        rs2 += __shfl_xor_sync(0xffffffffu, rs2, 1);
        rs2 += __shfl_xor_sync(0xffffffffu, rs2, 2);
        l1 = l1 * cr1 + rs1;  l2 = l2 * cr2 + rs2;   // denom WITHOUT dropout (matches ref)
        m1 = mn1;  m2 = mn2;
        #pragma unroll
        for (int nf = 0; nf < 16; nf++) {
            o[nf][0] *= cr1; o[nf][1] *= cr1;
            o[nf][2] *= cr2; o[nf][3] *= cr2;
        }

        // dropout on P
        #pragma unroll
        for (int nf = 0; nf < 8; nf++) {
            unsigned j0 = (unsigned)(jb * 64 + nf * 8 + (lane & 3) * 2);
            sc[nf][0] *= dropout_keep(ebase + (unsigned)ig1 * 2048u + j0);
            sc[nf][1] *= dropout_keep(ebase + (unsigned)ig1 * 2048u + j0 + 1u);
            sc[nf][2] *= dropout_keep(ebase + (unsigned)(ig1 + 8) * 2048u + j0);
            sc[nf][3] *= dropout_keep(ebase + (unsigned)(ig1 + 8) * 2048u + j0 + 1u);
        }

        // O += P V (P hi/lo in registers, V via ldmatrix.trans)
        #pragma unroll
        for (int ksj = 0; ksj < 4; ksj++) {
            uint32_t ahi[4], alo[4];
            #pragma unroll
            for (int half = 0; half < 2; half++) {
                int nf = 2 * ksj + half;
                __nv_bfloat16 h0 = __float2bfloat16(sc[nf][0]);
                __nv_bfloat16 h1 = __float2bfloat16(sc[nf][1]);
                __nv_bfloat16 h2 = __float2bfloat16(sc[nf][2]);
                __nv_bfloat16 h3 = __float2bfloat16(sc[nf][3]);
                __nv_bfloat162 hh01 = __halves2bfloat162(h0, h1);
                __nv_bfloat162 hh23 = __halves2bfloat162(h2, h3);
                ahi[2 * half]     = *reinterpret_cast<uint32_t*>(&hh01);
                ahi[2 * half + 1] = *reinterpret_cast<uint32_t*>(&hh23);
                __nv_bfloat162 ll01 = __halves2bfloat162(
                    __float2bfloat16(sc[nf][0] - __bfloat162float(h0)),
                    __float2bfloat16(sc[nf][1] - __bfloat162float(h1)));
                __nv_bfloat162 ll23 = __halves2bfloat162(
                    __float2bfloat16(sc[nf][2] - __bfloat162float(h2)),
                    __float2bfloat16(sc[nf][3] - __bfloat162float(h3)));
                alo[2 * half]     = *reinterpret_cast<uint32_t*>(&ll01);
                alo[2 * half + 1] = *reinterpret_cast<uint32_t*>(&ll23);
            }
            #pragma unroll
            for (int nfp = 0; nfp < 8; nfp++) {
                uint32_t vh4[4], vl4[4];
                int vr = ksj * 16 + v_row8;
                int vc = 2 * nfp + v_chb;
                ldsm4t(vh4[0], vh4[1], vh4[2], vh4[3], sb + A_VH + asw(vr, vc));
                ldsm4t(vl4[0], vl4[1], vl4[2], vl4[3], sb + A_VL + asw(vr, vc));
                mma16816(o[2 * nfp],     ahi, vh4);
                mma16816(o[2 * nfp],     ahi, vl4);
                mma16816(o[2 * nfp],     alo, vh4);
                mma16816(o[2 * nfp + 1], ahi, vh4 + 2);
                mma16816(o[2 * nfp + 1], ahi, vl4 + 2);
                mma16816(o[2 * nfp + 1], alo, vh4 + 2);
            }
        }
        __syncthreads();
    }

    // epilogue
    float inv1 = 1.f / l1, inv2 = 1.f / l2;
    long r1g = (long)(b * T_ + qb * 128 + qrw + (lane >> 2));
    #pragma unroll
    for (int nf = 0; nf < 16; nf++) {
        int col = hq * 128 + nf * 8 + (lane & 3) * 2;
        *(float2*)(O + r1g * 2048 + col)       = make_float2(o[nf][0] * inv1, o[nf][1] * inv1);
        *(float2*)(O + (r1g + 8) * 2048 + col) = make_float2(o[nf][2] * inv2, o[nf][3] * inv2);
    }
}

// ============================ launch ===========================================
extern "C" void kernel_launch(void* const* d_in, const int* in_sizes, int n_in,
                              void* d_out, int out_size) {
    const float* x  = (const float*)d_in[0];
    const float* wq = (const float*)d_in[1];
    const float* wk = (const float*)d_in[2];
    const float* wv = (const float*)d_in[3];
    const float* wo = (const float*)d_in[4];
    float* out = (float*)d_out;
    float* kv  = out + QELEMS;

    float *qp, *kp, *vp, *ap;
    cudaGetSymbolAddress((void**)&qp, g_q);
    cudaGetSymbolAddress((void**)&kp, g_kraw);
    cudaGetSymbolAddress((void**)&vp, g_vraw);
    cudaGetSymbolAddress((void**)&ap, g_attn);
    __nv_bfloat16 *xs0, *xs1, *wqT0, *wqT1, *wkT0, *wkT1, *wvT0, *wvT1, *woT0, *woT1;
    __nv_bfloat16 *aqh, *aql, *akh, *akl, *avh, *avl;
    cudaGetSymbolAddress((void**)&xs0, g_xs0);
    cudaGetSymbolAddress((void**)&xs1, g_xs1);
    cudaGetSymbolAddress((void**)&wqT0, g_wqT0);
    cudaGetSymbolAddress((void**)&wqT1, g_wqT1);
    cudaGetSymbolAddress((void**)&wkT0, g_wkT0);
    cudaGetSymbolAddress((void**)&wkT1, g_wkT1);
    cudaGetSymbolAddress((void**)&wvT0, g_wvT0);
    cudaGetSymbolAddress((void**)&wvT1, g_wvT1);
    cudaGetSymbolAddress((void**)&woT0, g_woT0);
    cudaGetSymbolAddress((void**)&woT1, g_woT1);
    cudaGetSymbolAddress((void**)&aqh, g_aqh);
    cudaGetSymbolAddress((void**)&aql, g_aql);
    cudaGetSymbolAddress((void**)&akh, g_akh);
    cudaGetSymbolAddress((void**)&akl, g_akl);
    cudaGetSymbolAddress((void**)&avh, g_avh);
    cudaGetSymbolAddress((void**)&avl, g_avl);

    cudaFuncSetAttribute(gemm_mma, cudaFuncAttributeMaxDynamicSharedMemorySize, GSM_TOT);
    cudaFuncSetAttribute(attn_mma, cudaFuncAttributeMaxDynamicSharedMemorySize, A_TOT);

    // prep
    split_f32<<<(MROWS * D_ / 4) / 256, 256>>>(x, xs0, xs1);
    wsplitT<<<dim3(D_ / 32, D_ / 32), dim3(32, 8)>>>(wq, wqT0, wqT1, D_);
    wsplitT<<<dim3(512 / 32, D_ / 32), dim3(32, 8)>>>(wk, wkT0, wkT1, 512);
    wsplitT<<<dim3(512 / 32, D_ / 32), dim3(32, 8)>>>(wv, wvT0, wvT1, 512);
    wsplitT<<<dim3(D_ / 32, D_ / 32), dim3(32, 8)>>>(wo, woT0, woT1, D_);

    // projections (tensor pipe)
    gemm_mma<<<dim3(D_ / 64, MROWS / 128), 256, GSM_TOT>>>(xs0, xs1, wqT0, wqT1, qp, D_);
    gemm_mma<<<dim3(512 / 64, MROWS / 128), 256, GSM_TOT>>>(xs0, xs1, wkT0, wkT1, kp, 512);
    gemm_mma<<<dim3(512 / 64, MROWS / 128), 256, GSM_TOT>>>(xs0, xs1, wvT0, wvT1, vp, 512);

    rope_pack<<<(MROWS * HQ_ * 64) / 256, 256>>>(qp, kp, vp, kv, aqh, aql, akh, akl, avh, avl);

    // tensor-core attention
    attn_mma<<<dim3(T_ / 128, B_ * HQ_), 256, A_TOT>>>(aqh, aql, akh, akl, avh, avl, ap);

    // out projection
    split_f32<<<(MROWS * D_ / 4) / 256, 256>>>(ap, xs0, xs1);
    gemm_mma<<<dim3(D_ / 64, MROWS / 128), 256, GSM_TOT>>>(xs0, xs1, woT0, woT1, out, D_);
}